// round 6
// baseline (speedup 1.0000x reference)
#include <cuda_runtime.h>
#include <cstdint>
#include <cstddef>

// Bidirectional tanh RNN. N=8, L=4096, C=H=256.
// 16 sequences (8 batch x 2 dir) x 8-CTA clusters; CTA owns 32 hidden units.
// Sync mechanism: NONE. Producers push LSB-tagged h values with plain weak
// st.shared::cluster; consumers poll the exact words they will consume
// (flag-in-data). No mbarriers, no cluster barriers, no __syncthreads in loop.

constexpr int L_DIM   = 4096;
constexpr int C_DIM   = 256;
constexpr int H_DIM   = 256;
constexpr int CLUSTER = 8;
constexpr int THREADS = 256;              // 8 warps; warp owns 4 units
constexpr int SLICE   = 36;               // 32 data floats + 4 pad (kills 8-way LDS conflicts)
constexpr int HP      = CLUSTER * SLICE;  // 288 floats per h buffer

__device__ __forceinline__ uint32_t smem_u32(const void* p) {
    return (uint32_t)__cvta_generic_to_shared(p);
}

__device__ __forceinline__ float fast_tanh(float z) {
    float e = __expf(2.0f * z);           // MUFU path, ~1e-6 rel err
    return 1.0f - 2.0f / (e + 1.0f);
}

// Spin until all 32 words of the needed peer slice carry LSB tag == ep.
// efull = ep ? 0xFFFFFFFF : 0.  The loaded words ARE the h data (flag-in-data).
__device__ __forceinline__ void poll_slice(uint32_t u[32], uint32_t base, uint32_t efull)
{
    for (;;) {
#pragma unroll
        for (int k = 0; k < 8; k++) {
            asm volatile("ld.volatile.shared.v4.b32 {%0,%1,%2,%3}, [%4];"
                : "=r"(u[4*k+0]), "=r"(u[4*k+1]), "=r"(u[4*k+2]), "=r"(u[4*k+3])
                : "r"(base + 16u * k));
        }
        uint32_t m = 0;
#pragma unroll
        for (int i = 0; i < 32; i++) m |= (u[i] ^ efull);
        if (!(m & 1u)) return;
    }
}

struct StepCtx {
    const float* wi;   // pointer to wi[32] regs (array passed by ref below)
};

// One recurrence sub-step. xr is consumed then refilled with the next row.
__device__ __forceinline__ float do_substep(
    float4 xr[8], bool pre_ok, const float* pnext_thread,
    const float wi[32], const float wh[32], float bsum,
    uint32_t poll_base, uint32_t efull, uint32_t epush,
    bool do_push, uint32_t push_addr, int lane)
{
    // u = W_ih . x_t  (h-independent, runs before the poll)
    float a0 = 0.f, a1 = 0.f, a2 = 0.f, a3 = 0.f;
#pragma unroll
    for (int k = 0; k < 8; k++) {
        float4 t = xr[k];
        a0 = fmaf(wi[4*k+0], t.x, a0);
        a1 = fmaf(wi[4*k+1], t.y, a1);
        a2 = fmaf(wi[4*k+2], t.z, a2);
        a3 = fmaf(wi[4*k+3], t.w, a3);
    }
    // prefetch next x row into the (now free) registers; L2 latency hidden
    if (pre_ok) {
        const float4* p = reinterpret_cast<const float4*>(pnext_thread);
#pragma unroll
        for (int k = 0; k < 8; k++) xr[k] = p[k];
    }

    // wait for + load h(s-1) slice (the poll IS the read)
    uint32_t u[32];
    poll_slice(u, poll_base, efull);

    // v += W_hh . h
#pragma unroll
    for (int k = 0; k < 8; k++) {
        a0 = fmaf(wh[4*k+0], __uint_as_float(u[4*k+0]), a0);
        a1 = fmaf(wh[4*k+1], __uint_as_float(u[4*k+1]), a1);
        a2 = fmaf(wh[4*k+2], __uint_as_float(u[4*k+2]), a2);
        a3 = fmaf(wh[4*k+3], __uint_as_float(u[4*k+3]), a3);
    }
    float acc = (a0 + a1) + (a2 + a3);
    acc += __shfl_xor_sync(0xffffffffu, acc, 16);
    acc += __shfl_xor_sync(0xffffffffu, acc, 8);
    acc += __shfl_xor_sync(0xffffffffu, acc, 4);
    const float hn = fast_tanh(acc + bsum);

    // encode LSB tag, assemble the warp's v4, push to all 8 CTAs in ONE store
    const uint32_t en = (__float_as_uint(hn) & ~1u) | epush;
    const uint32_t e0 = __shfl_sync(0xffffffffu, en, 0);
    const uint32_t e1 = __shfl_sync(0xffffffffu, en, 1);
    const uint32_t e2 = __shfl_sync(0xffffffffu, en, 2);
    const uint32_t e3 = __shfl_sync(0xffffffffu, en, 3);
    if (do_push && lane < CLUSTER) {
        asm volatile("st.shared::cluster.v4.b32 [%0], {%1,%2,%3,%4};"
                     :: "r"(push_addr), "r"(e0), "r"(e1), "r"(e2), "r"(e3)
                     : "memory");
    }
    return hn;
}

__global__ void __launch_bounds__(THREADS, 1) __cluster_dims__(CLUSTER, 1, 1)
rnn_bidir_kernel(const float* __restrict__ x,
                 const float* __restrict__ Wih,
                 const float* __restrict__ Whh,
                 const float* __restrict__ bih,
                 const float* __restrict__ bhh,
                 const float* __restrict__ init_states,
                 float* __restrict__ out)
{
    __shared__ __align__(16) float h_buf[2][HP];

    const int tid  = threadIdx.x;
    const int w    = tid >> 5;
    const int lane = tid & 31;
    const int jj   = (w << 2) | (lane & 3);   // unit within CTA slice (0..31)
    const int c    = lane >> 2;               // K-chunk / source-peer id (0..7)

    uint32_t rank_u;
    asm("mov.u32 %0, %%cluster_ctarank;" : "=r"(rank_u));
    const int rank = (int)rank_u;

    const int seq = blockIdx.x >> 3;          // 0..15
    const int n   = seq & 7;
    const int dir = seq >> 3;

    const int j  = rank * (H_DIM / CLUSTER) + jj;   // global hidden unit
    const int i0 = c * 32;

    // ---- weight slices into registers ----
    float wh[32], wi[32];
    {
        const float4* p = reinterpret_cast<const float4*>(Whh + (size_t)j * H_DIM + i0);
        const float4* q = reinterpret_cast<const float4*>(Wih + (size_t)j * C_DIM + i0);
#pragma unroll
        for (int k = 0; k < 8; k++) {
            float4 a = p[k];
            wh[4*k+0] = a.x; wh[4*k+1] = a.y; wh[4*k+2] = a.z; wh[4*k+3] = a.w;
            float4 b = q[k];
            wi[4*k+0] = b.x; wi[4*k+1] = b.y; wi[4*k+2] = b.z; wi[4*k+3] = b.w;
        }
    }
    const float bsum = bih[j] + bhh[j];
    const float* xbase = x + (size_t)n * L_DIM * C_DIM;

    // ---- init h buffers ----
    // buf0 <- init_states with LSB tag 0 (poll at s=0 expects 0, passes instantly)
    // buf1 <- poison LSB 1 (poll at s=1 expects 0, blocks until real h(0) lands)
    if (tid < H_DIM) {
        const int off = (tid >> 5) * SLICE + (tid & 31);
        h_buf[0][off] = __uint_as_float(__float_as_uint(init_states[tid]) & ~1u);
        h_buf[1][off] = __uint_as_float(1u);
    }
    __syncthreads();
    // one-time: all CTAs resident + local buffers initialized before any remote store
    asm volatile("barrier.cluster.arrive.aligned;" ::: "memory");
    asm volatile("barrier.cluster.wait.aligned;"   ::: "memory");

    // ---- addresses ----
    const uint32_t pb0 = smem_u32(&h_buf[0][c * SLICE]);   // slice this thread consumes
    const uint32_t pb1 = smem_u32(&h_buf[1][c * SLICE]);
    uint32_t rh0, rh1;                                     // per-lane remote push slots
    {
        const uint32_t lp0 = smem_u32(&h_buf[0][rank * SLICE + 4 * w]);
        const uint32_t lp1 = smem_u32(&h_buf[1][rank * SLICE + 4 * w]);
        const uint32_t tgt = (uint32_t)(lane & 7);         // lanes >=8 get valid unused addrs
        asm volatile("mapa.shared::cluster.u32 %0, %1, %2;" : "=r"(rh0) : "r"(lp0), "r"(tgt));
        asm volatile("mapa.shared::cluster.u32 %0, %1, %2;" : "=r"(rh1) : "r"(lp1), "r"(tgt));
    }

    // ---- x row registers: load row 0, pointer at row 1 ----
    const int ll0 = dir ? (L_DIM - 1) : 0;
    const ptrdiff_t xstep = (dir ? -1 : 1) * (ptrdiff_t)C_DIM;
    float4 xr[8];
    {
        const float4* p = reinterpret_cast<const float4*>(xbase + (size_t)ll0 * C_DIM + i0);
#pragma unroll
        for (int k = 0; k < 8; k++) xr[k] = p[k];
    }
    const float* pnext = xbase + (size_t)ll0 * C_DIM + i0 + xstep;

    float* optr = out + ((size_t)(n * L_DIM + ll0)) * (2 * H_DIM) + dir * H_DIM + j;
    const ptrdiff_t ostep = (dir ? -1 : 1) * (ptrdiff_t)(2 * H_DIM);

    uint32_t ep = 0;   // (s>>1)&1 for the current even step; toggles per iteration

#pragma unroll 1
    for (int s = 0; s < L_DIM; s += 2) {
        const uint32_t efull = 0u - ep;       // 0 or 0xFFFFFFFF
        const bool last = (s + 2 >= L_DIM);

        // even sub-step: poll buf0 (tag ep), push h -> buf1 (tag ep)
        float hn0 = do_substep(xr, true, pnext, wi, wh, bsum,
                               pb0, efull, ep, true, rh1, lane);
        pnext += xstep;
        if (lane < 4) *optr = hn0;
        optr += ostep;

        // odd sub-step: poll buf1 (tag ep), push h -> buf0 (tag ep^1)
        float hn1 = do_substep(xr, !last, pnext, wi, wh, bsum,
                               pb1, efull, ep ^ 1u, !last, rh0, lane);
        pnext += xstep;
        if (lane < 4) *optr = hn1;
        optr += ostep;

        ep ^= 1u;
    }

    // no remote traffic in flight (final push skipped); keep smem alive
    asm volatile("barrier.cluster.arrive.aligned;" ::: "memory");
    asm volatile("barrier.cluster.wait.aligned;"   ::: "memory");
}

extern "C" void kernel_launch(void* const* d_in, const int* in_sizes, int n_in,
                              void* d_out, int out_size)
{
    (void)in_sizes; (void)n_in; (void)out_size;
    const float* x    = (const float*)d_in[0];
    const float* Wih  = (const float*)d_in[1];
    const float* Whh  = (const float*)d_in[2];
    const float* bih  = (const float*)d_in[3];
    const float* bhh  = (const float*)d_in[4];
    const float* init = (const float*)d_in[5];
    float* out = (float*)d_out;

    rnn_bidir_kernel<<<16 * CLUSTER, THREADS>>>(x, Wih, Whh, bih, bhh, init, out);
}

// round 7
// speedup vs baseline: 1.0009x; 1.0009x over previous
#include <cuda_runtime.h>
#include <cstdint>
#include <cstddef>

// Bidirectional tanh RNN. N=8, L=4096, C=H=256.
// 16 sequences (8 batch x 2 dir) x 8-CTA clusters; CTA owns 32 hidden units.
// Sync mechanism: NONE. Producers push LSB-tagged h values with plain weak
// st.shared::cluster; consumers poll the exact words they will consume
// (flag-in-data). No mbarriers, no cluster barriers, no __syncthreads in loop.

constexpr int L_DIM   = 4096;
constexpr int C_DIM   = 256;
constexpr int H_DIM   = 256;
constexpr int CLUSTER = 8;
constexpr int THREADS = 256;              // 8 warps; warp owns 4 units
constexpr int SLICE   = 36;               // 32 data floats + 4 pad (kills 8-way LDS conflicts)
constexpr int HP      = CLUSTER * SLICE;  // 288 floats per h buffer

__device__ __forceinline__ uint32_t smem_u32(const void* p) {
    return (uint32_t)__cvta_generic_to_shared(p);
}

__device__ __forceinline__ float fast_tanh(float z) {
    float e = __expf(2.0f * z);           // MUFU path, ~1e-6 rel err
    return 1.0f - 2.0f / (e + 1.0f);
}

// Spin until all 32 words of the needed peer slice carry LSB tag == ep.
// efull = ep ? 0xFFFFFFFF : 0.  The loaded words ARE the h data (flag-in-data).
__device__ __forceinline__ void poll_slice(uint32_t u[32], uint32_t base, uint32_t efull)
{
    for (;;) {
#pragma unroll
        for (int k = 0; k < 8; k++) {
            asm volatile("ld.volatile.shared.v4.b32 {%0,%1,%2,%3}, [%4];"
                : "=r"(u[4*k+0]), "=r"(u[4*k+1]), "=r"(u[4*k+2]), "=r"(u[4*k+3])
                : "r"(base + 16u * k));
        }
        uint32_t m = 0;
#pragma unroll
        for (int i = 0; i < 32; i++) m |= (u[i] ^ efull);
        if (!(m & 1u)) return;
    }
}

struct StepCtx {
    const float* wi;   // pointer to wi[32] regs (array passed by ref below)
};

// One recurrence sub-step. xr is consumed then refilled with the next row.
__device__ __forceinline__ float do_substep(
    float4 xr[8], bool pre_ok, const float* pnext_thread,
    const float wi[32], const float wh[32], float bsum,
    uint32_t poll_base, uint32_t efull, uint32_t epush,
    bool do_push, uint32_t push_addr, int lane)
{
    // u = W_ih . x_t  (h-independent, runs before the poll)
    float a0 = 0.f, a1 = 0.f, a2 = 0.f, a3 = 0.f;
#pragma unroll
    for (int k = 0; k < 8; k++) {
        float4 t = xr[k];
        a0 = fmaf(wi[4*k+0], t.x, a0);
        a1 = fmaf(wi[4*k+1], t.y, a1);
        a2 = fmaf(wi[4*k+2], t.z, a2);
        a3 = fmaf(wi[4*k+3], t.w, a3);
    }
    // prefetch next x row into the (now free) registers; L2 latency hidden
    if (pre_ok) {
        const float4* p = reinterpret_cast<const float4*>(pnext_thread);
#pragma unroll
        for (int k = 0; k < 8; k++) xr[k] = p[k];
    }

    // wait for + load h(s-1) slice (the poll IS the read)
    uint32_t u[32];
    poll_slice(u, poll_base, efull);

    // v += W_hh . h
#pragma unroll
    for (int k = 0; k < 8; k++) {
        a0 = fmaf(wh[4*k+0], __uint_as_float(u[4*k+0]), a0);
        a1 = fmaf(wh[4*k+1], __uint_as_float(u[4*k+1]), a1);
        a2 = fmaf(wh[4*k+2], __uint_as_float(u[4*k+2]), a2);
        a3 = fmaf(wh[4*k+3], __uint_as_float(u[4*k+3]), a3);
    }
    float acc = (a0 + a1) + (a2 + a3);
    acc += __shfl_xor_sync(0xffffffffu, acc, 16);
    acc += __shfl_xor_sync(0xffffffffu, acc, 8);
    acc += __shfl_xor_sync(0xffffffffu, acc, 4);
    const float hn = fast_tanh(acc + bsum);

    // encode LSB tag, assemble the warp's v4, push to all 8 CTAs in ONE store
    const uint32_t en = (__float_as_uint(hn) & ~1u) | epush;
    const uint32_t e0 = __shfl_sync(0xffffffffu, en, 0);
    const uint32_t e1 = __shfl_sync(0xffffffffu, en, 1);
    const uint32_t e2 = __shfl_sync(0xffffffffu, en, 2);
    const uint32_t e3 = __shfl_sync(0xffffffffu, en, 3);
    if (do_push && lane < CLUSTER) {
        asm volatile("st.shared::cluster.v4.b32 [%0], {%1,%2,%3,%4};"
                     :: "r"(push_addr), "r"(e0), "r"(e1), "r"(e2), "r"(e3)
                     : "memory");
    }
    return hn;
}

__global__ void __launch_bounds__(THREADS, 1) __cluster_dims__(CLUSTER, 1, 1)
rnn_bidir_kernel(const float* __restrict__ x,
                 const float* __restrict__ Wih,
                 const float* __restrict__ Whh,
                 const float* __restrict__ bih,
                 const float* __restrict__ bhh,
                 const float* __restrict__ init_states,
                 float* __restrict__ out)
{
    __shared__ __align__(16) float h_buf[2][HP];

    const int tid  = threadIdx.x;
    const int w    = tid >> 5;
    const int lane = tid & 31;
    const int jj   = (w << 2) | (lane & 3);   // unit within CTA slice (0..31)
    const int c    = lane >> 2;               // K-chunk / source-peer id (0..7)

    uint32_t rank_u;
    asm("mov.u32 %0, %%cluster_ctarank;" : "=r"(rank_u));
    const int rank = (int)rank_u;

    const int seq = blockIdx.x >> 3;          // 0..15
    const int n   = seq & 7;
    const int dir = seq >> 3;

    const int j  = rank * (H_DIM / CLUSTER) + jj;   // global hidden unit
    const int i0 = c * 32;

    // ---- weight slices into registers ----
    float wh[32], wi[32];
    {
        const float4* p = reinterpret_cast<const float4*>(Whh + (size_t)j * H_DIM + i0);
        const float4* q = reinterpret_cast<const float4*>(Wih + (size_t)j * C_DIM + i0);
#pragma unroll
        for (int k = 0; k < 8; k++) {
            float4 a = p[k];
            wh[4*k+0] = a.x; wh[4*k+1] = a.y; wh[4*k+2] = a.z; wh[4*k+3] = a.w;
            float4 b = q[k];
            wi[4*k+0] = b.x; wi[4*k+1] = b.y; wi[4*k+2] = b.z; wi[4*k+3] = b.w;
        }
    }
    const float bsum = bih[j] + bhh[j];
    const float* xbase = x + (size_t)n * L_DIM * C_DIM;

    // ---- init h buffers ----
    // buf0 <- init_states with LSB tag 0 (poll at s=0 expects 0, passes instantly)
    // buf1 <- poison LSB 1 (poll at s=1 expects 0, blocks until real h(0) lands)
    if (tid < H_DIM) {
        const int off = (tid >> 5) * SLICE + (tid & 31);
        h_buf[0][off] = __uint_as_float(__float_as_uint(init_states[tid]) & ~1u);
        h_buf[1][off] = __uint_as_float(1u);
    }
    __syncthreads();
    // one-time: all CTAs resident + local buffers initialized before any remote store
    asm volatile("barrier.cluster.arrive.aligned;" ::: "memory");
    asm volatile("barrier.cluster.wait.aligned;"   ::: "memory");

    // ---- addresses ----
    const uint32_t pb0 = smem_u32(&h_buf[0][c * SLICE]);   // slice this thread consumes
    const uint32_t pb1 = smem_u32(&h_buf[1][c * SLICE]);
    uint32_t rh0, rh1;                                     // per-lane remote push slots
    {
        const uint32_t lp0 = smem_u32(&h_buf[0][rank * SLICE + 4 * w]);
        const uint32_t lp1 = smem_u32(&h_buf[1][rank * SLICE + 4 * w]);
        const uint32_t tgt = (uint32_t)(lane & 7);         // lanes >=8 get valid unused addrs
        asm volatile("mapa.shared::cluster.u32 %0, %1, %2;" : "=r"(rh0) : "r"(lp0), "r"(tgt));
        asm volatile("mapa.shared::cluster.u32 %0, %1, %2;" : "=r"(rh1) : "r"(lp1), "r"(tgt));
    }

    // ---- x row registers: load row 0, pointer at row 1 ----
    const int ll0 = dir ? (L_DIM - 1) : 0;
    const ptrdiff_t xstep = (dir ? -1 : 1) * (ptrdiff_t)C_DIM;
    float4 xr[8];
    {
        const float4* p = reinterpret_cast<const float4*>(xbase + (size_t)ll0 * C_DIM + i0);
#pragma unroll
        for (int k = 0; k < 8; k++) xr[k] = p[k];
    }
    const float* pnext = xbase + (size_t)ll0 * C_DIM + i0 + xstep;

    float* optr = out + ((size_t)(n * L_DIM + ll0)) * (2 * H_DIM) + dir * H_DIM + j;
    const ptrdiff_t ostep = (dir ? -1 : 1) * (ptrdiff_t)(2 * H_DIM);

    uint32_t ep = 0;   // (s>>1)&1 for the current even step; toggles per iteration

#pragma unroll 1
    for (int s = 0; s < L_DIM; s += 2) {
        const uint32_t efull = 0u - ep;       // 0 or 0xFFFFFFFF
        const bool last = (s + 2 >= L_DIM);

        // even sub-step: poll buf0 (tag ep), push h -> buf1 (tag ep)
        float hn0 = do_substep(xr, true, pnext, wi, wh, bsum,
                               pb0, efull, ep, true, rh1, lane);
        pnext += xstep;
        if (lane < 4) *optr = hn0;
        optr += ostep;

        // odd sub-step: poll buf1 (tag ep), push h -> buf0 (tag ep^1)
        float hn1 = do_substep(xr, !last, pnext, wi, wh, bsum,
                               pb1, efull, ep ^ 1u, !last, rh0, lane);
        pnext += xstep;
        if (lane < 4) *optr = hn1;
        optr += ostep;

        ep ^= 1u;
    }

    // no remote traffic in flight (final push skipped); keep smem alive
    asm volatile("barrier.cluster.arrive.aligned;" ::: "memory");
    asm volatile("barrier.cluster.wait.aligned;"   ::: "memory");
}

extern "C" void kernel_launch(void* const* d_in, const int* in_sizes, int n_in,
                              void* d_out, int out_size)
{
    (void)in_sizes; (void)n_in; (void)out_size;
    const float* x    = (const float*)d_in[0];
    const float* Wih  = (const float*)d_in[1];
    const float* Whh  = (const float*)d_in[2];
    const float* bih  = (const float*)d_in[3];
    const float* bhh  = (const float*)d_in[4];
    const float* init = (const float*)d_in[5];
    float* out = (float*)d_out;

    rnn_bidir_kernel<<<16 * CLUSTER, THREADS>>>(x, Wih, Whh, bih, bhh, init, out);
}